// round 1
// baseline (speedup 1.0000x reference)
#include <cuda_runtime.h>

#define S 2048
#define F 1024
#define H 16
#define DH 64
#define NHD 1024  // H*DH

// Scratch (device globals: allocation-free per harness rules)
__device__ float g_q[S * NHD];
__device__ float g_k[S * NHD];
__device__ float g_v[S * NHD];
__device__ float g_r[S * NHD];
__device__ float g_attn[S * NHD];

// ---------------------------------------------------------------------------
// Generic fp32 SGEMM body: C[M,N] = A[M,K] @ B[K,N] + bias[N]
// 128x128 block tile, K-tile 8, 256 threads, 8x8 per-thread micro-tile.
// ---------------------------------------------------------------------------
__device__ __forceinline__ void sgemm_body(
    const float* __restrict__ A, const float* __restrict__ B,
    const float* __restrict__ bias, float* __restrict__ C,
    int M, int N, int K)
{
    __shared__ float As[8][128];
    __shared__ float Bs[8][128];

    const int t  = threadIdx.x;
    const int tx = t & 15;
    const int ty = t >> 4;
    const int m0 = blockIdx.y * 128;
    const int n0 = blockIdx.x * 128;

    float acc[8][8];
#pragma unroll
    for (int r = 0; r < 8; r++)
#pragma unroll
        for (int c = 0; c < 8; c++) acc[r][c] = 0.f;

    const int arow = t >> 1;          // 0..127
    const int acol = (t & 1) * 4;     // 0 or 4
    const int brow = t >> 5;          // 0..7
    const int bcol = (t & 31) * 4;    // 0..124

    for (int k0 = 0; k0 < K; k0 += 8) {
        float4 av = *(const float4*)(A + (size_t)(m0 + arow) * K + k0 + acol);
        As[acol + 0][arow] = av.x;
        As[acol + 1][arow] = av.y;
        As[acol + 2][arow] = av.z;
        As[acol + 3][arow] = av.w;
        *(float4*)&Bs[brow][bcol] =
            *(const float4*)(B + (size_t)(k0 + brow) * N + n0 + bcol);
        __syncthreads();

#pragma unroll
        for (int kk = 0; kk < 8; kk++) {
            float a[8], b[8];
            *(float4*)&a[0] = *(const float4*)&As[kk][ty * 8];
            *(float4*)&a[4] = *(const float4*)&As[kk][ty * 8 + 4];
            *(float4*)&b[0] = *(const float4*)&Bs[kk][tx * 8];
            *(float4*)&b[4] = *(const float4*)&Bs[kk][tx * 8 + 4];
#pragma unroll
            for (int r = 0; r < 8; r++)
#pragma unroll
                for (int c = 0; c < 8; c++)
                    acc[r][c] = fmaf(a[r], b[c], acc[r][c]);
        }
        __syncthreads();
    }

#pragma unroll
    for (int r = 0; r < 8; r++) {
        const int row = m0 + ty * 8 + r;
#pragma unroll
        for (int c = 0; c < 8; c += 4) {
            const int col = n0 + tx * 8 + c;
            float4 o;
            o.x = acc[r][c + 0] + bias[col + 0];
            o.y = acc[r][c + 1] + bias[col + 1];
            o.z = acc[r][c + 2] + bias[col + 2];
            o.w = acc[r][c + 3] + bias[col + 3];
            *(float4*)(C + (size_t)row * N + col) = o;
        }
    }
}

// Batched q/k/v/r projection: z selects which GEMM.
__global__ __launch_bounds__(256, 2) void proj_kernel(
    const float* __restrict__ Xq, const float* __restrict__ Xr,
    const float* __restrict__ Wq, const float* __restrict__ Wk,
    const float* __restrict__ Wv, const float* __restrict__ Wr,
    const float* __restrict__ bq, const float* __restrict__ bk,
    const float* __restrict__ bv, const float* __restrict__ br)
{
    const float* A;
    const float* B;
    const float* bias;
    float* C;
    switch (blockIdx.z) {
        case 0:  A = Xq; B = Wq; bias = bq; C = g_q; break;
        case 1:  A = Xq; B = Wk; bias = bk; C = g_k; break;
        case 2:  A = Xq; B = Wv; bias = bv; C = g_v; break;
        default: A = Xr; B = Wr; bias = br; C = g_r; break;
    }
    sgemm_body(A, B, bias, C, S, NHD, F);
}

// Output projection: d_out = g_attn @ Wo + bo
__global__ __launch_bounds__(256, 2) void out_kernel(
    const float* __restrict__ Wo, const float* __restrict__ bo,
    float* __restrict__ out)
{
    sgemm_body(g_attn, Wo, bo, out, S, F, NHD);
}

// ---------------------------------------------------------------------------
// Causal flash attention with Transformer-XL relative position term.
// score[i,j] = ((q_i+rw)·k_j + (q_i+rr)·r_key[S-1+j-i]) / 8   (j <= i)
// Grid: (S/64 qtiles, H). 256 threads, 4x4 micro-tile of the 64x64 score tile.
// ---------------------------------------------------------------------------
__global__ __launch_bounds__(256, 1) void attn_kernel(
    const float* __restrict__ rwb, const float* __restrict__ rrb)
{
    const int h = blockIdx.y;
    // heavier query tiles first (more key tiles) for better tail behavior
    const int qi0 = (gridDim.x - 1 - blockIdx.x) * 64;

    extern __shared__ float sm[];
    float* qw = sm;               // 64x64  (q + r_w_bias)
    float* qr = qw + 64 * 64;     // 64x64  (q + r_r_bias)
    float* kt = qr + 64 * 64;     // 64x64  key tile; reused as P tile
    float* vt = kt + 64 * 64;     // 64x64  value tile
    float* rs = vt + 64 * 64;     // 127x64 r_key diagonal slab

    const int t    = threadIdx.x;
    const int tx   = t & 15;
    const int ty   = t >> 4;
    const int row0 = ty * 4;
    const int col0 = tx * 4;
    const int hb   = h * DH;

    // load q tile, fuse in the two biases
    for (int idx = t; idx < 64 * 16; idx += 256) {
        const int r = idx >> 4;
        const int d = (idx & 15) << 2;
        float4 qv = *(const float4*)&g_q[(size_t)(qi0 + r) * NHD + hb + d];
        float4 w  = *(const float4*)&rwb[hb + d];
        float4 rr = *(const float4*)&rrb[hb + d];
        float4 a, b;
        a.x = qv.x + w.x;  a.y = qv.y + w.y;  a.z = qv.z + w.z;  a.w = qv.w + w.w;
        b.x = qv.x + rr.x; b.y = qv.y + rr.y; b.z = qv.z + rr.z; b.w = qv.w + rr.w;
        *(float4*)&qw[r * 64 + d] = a;
        *(float4*)&qr[r * 64 + d] = b;
    }

    float m_i[4], l_i[4], oa[4][4];
#pragma unroll
    for (int r = 0; r < 4; r++) {
        m_i[r] = -1e30f;
        l_i[r] = 0.f;
#pragma unroll
        for (int c = 0; c < 4; c++) oa[r][c] = 0.f;
    }

    const int nkt = qi0 / 64 + 1;
    const int mmb = 63 + col0 - row0;  // rs row for (r,c) is mmb + c - r

    for (int ktile = 0; ktile < nkt; ++ktile) {
        const int kj0 = ktile * 64;
        __syncthreads();  // protect kt/vt/rs (and first-iter q stores)

        // load key/value tiles
        for (int idx = t; idx < 64 * 16; idx += 256) {
            const int r = idx >> 4;
            const int d = (idx & 15) << 2;
            *(float4*)&kt[r * 64 + d] =
                *(const float4*)&g_k[(size_t)(kj0 + r) * NHD + hb + d];
            *(float4*)&vt[r * 64 + d] =
                *(const float4*)&g_v[(size_t)(kj0 + r) * NHD + hb + d];
        }
        // load r_key slab: rows base..base+126 (clamped; overflow rows are masked)
        const int base = (S - 1) + kj0 - qi0 - 63;
        for (int idx = t; idx < 127 * 16; idx += 256) {
            const int mm = idx >> 4;
            const int d  = (idx & 15) << 2;
            int mg = base + mm;
            if (mg > S - 1) mg = S - 1;
            *(float4*)&rs[mm * 64 + d] =
                *(const float4*)&g_r[(size_t)mg * NHD + hb + d];
        }
        __syncthreads();

        // ---- scores: AC + BD (diagonal gather) ----
        float sc[4][4];
#pragma unroll
        for (int r = 0; r < 4; r++)
#pragma unroll
            for (int c = 0; c < 4; c++) sc[r][c] = 0.f;

        for (int d = 0; d < 64; d += 4) {
            float aw[4][4], ar[4][4], bk[4][4], rv[7][4];
#pragma unroll
            for (int r = 0; r < 4; r++) {
                *(float4*)aw[r] = *(const float4*)&qw[(row0 + r) * 64 + d];
                *(float4*)ar[r] = *(const float4*)&qr[(row0 + r) * 64 + d];
                *(float4*)bk[r] = *(const float4*)&kt[(col0 + r) * 64 + d];
            }
#pragma unroll
            for (int u = 0; u < 7; u++)
                *(float4*)rv[u] = *(const float4*)&rs[(mmb - 3 + u) * 64 + d];
#pragma unroll
            for (int r = 0; r < 4; r++)
#pragma unroll
                for (int c = 0; c < 4; c++) {
                    float s = sc[r][c];
#pragma unroll
                    for (int e = 0; e < 4; e++)
                        s = fmaf(aw[r][e], bk[c][e],
                                 fmaf(ar[r][e], rv[3 + c - r][e], s));
                    sc[r][c] = s;
                }
        }

        // ---- online softmax (scale 1/sqrt(64) = 0.125, causal mask on diag tile) ----
        const bool diag = (ktile == nkt - 1);
#pragma unroll
        for (int r = 0; r < 4; r++) {
            float rmax = -1e30f;
#pragma unroll
            for (int c = 0; c < 4; c++) {
                float s = sc[r][c] * 0.125f;
                if (diag && (col0 + c) > (row0 + r)) s = -1e30f;
                sc[r][c] = s;
                rmax = fmaxf(rmax, s);
            }
#pragma unroll
            for (int off = 8; off > 0; off >>= 1)
                rmax = fmaxf(rmax, __shfl_xor_sync(0xffffffffu, rmax, off));
            const float newm  = fmaxf(m_i[r], rmax);
            const float alpha = __expf(m_i[r] - newm);
            m_i[r] = newm;
            float psum = 0.f;
#pragma unroll
            for (int c = 0; c < 4; c++) {
                const float p = __expf(sc[r][c] - newm);
                sc[r][c] = p;
                psum += p;
            }
#pragma unroll
            for (int off = 8; off > 0; off >>= 1)
                psum += __shfl_xor_sync(0xffffffffu, psum, off);
            l_i[r] = l_i[r] * alpha + psum;
#pragma unroll
            for (int c = 0; c < 4; c++) oa[r][c] *= alpha;
        }

        // ---- P @ V (P reuses the kt buffer) ----
        __syncthreads();  // everyone done reading kt
        float* ps = kt;
#pragma unroll
        for (int r = 0; r < 4; r++)
            *(float4*)&ps[(row0 + r) * 64 + col0] = *(float4*)sc[r];
        __syncthreads();

#pragma unroll 8
        for (int k = 0; k < 64; k++) {
            const float4 vv = *(const float4*)&vt[k * 64 + col0];
            float p[4];
#pragma unroll
            for (int r = 0; r < 4; r++) p[r] = ps[(row0 + r) * 64 + k];
#pragma unroll
            for (int r = 0; r < 4; r++) {
                oa[r][0] = fmaf(p[r], vv.x, oa[r][0]);
                oa[r][1] = fmaf(p[r], vv.y, oa[r][1]);
                oa[r][2] = fmaf(p[r], vv.z, oa[r][2]);
                oa[r][3] = fmaf(p[r], vv.w, oa[r][3]);
            }
        }
    }

    // ---- epilogue: normalize and store [s, h*64+d] ----
#pragma unroll
    for (int r = 0; r < 4; r++) {
        const float inv = 1.f / l_i[r];
        float4 o;
        o.x = oa[r][0] * inv;
        o.y = oa[r][1] * inv;
        o.z = oa[r][2] * inv;
        o.w = oa[r][3] * inv;
        *(float4*)&g_attn[(size_t)(qi0 + row0 + r) * NHD + hb + col0] = o;
    }
}

// ---------------------------------------------------------------------------
extern "C" void kernel_launch(void* const* d_in, const int* in_sizes, int n_in,
                              void* d_out, int out_size)
{
    const float* inputs_q = (const float*)d_in[0];
    const float* pos_emb  = (const float*)d_in[1];
    const float* r_w_bias = (const float*)d_in[2];
    const float* r_r_bias = (const float*)d_in[3];
    const float* Wq = (const float*)d_in[4];
    const float* bq = (const float*)d_in[5];
    const float* Wk = (const float*)d_in[6];
    const float* bk = (const float*)d_in[7];
    const float* Wv = (const float*)d_in[8];
    const float* bv = (const float*)d_in[9];
    const float* Wr = (const float*)d_in[10];
    const float* br = (const float*)d_in[11];
    const float* Wo = (const float*)d_in[12];
    const float* bo = (const float*)d_in[13];
    float* out = (float*)d_out;

    const int smem_attn = (4 * 64 * 64 + 127 * 64) * (int)sizeof(float);  // 98048
    cudaFuncSetAttribute(attn_kernel,
                         cudaFuncAttributeMaxDynamicSharedMemorySize, smem_attn);

    // 1) q/k/v/r projections (one batched launch, 512 blocks)
    proj_kernel<<<dim3(NHD / 128, S / 128, 4), 256>>>(
        inputs_q, pos_emb, Wq, Wk, Wv, Wr, bq, bk, bv, br);

    // 2) fused causal attention with relative-shift BD term
    attn_kernel<<<dim3(S / 64, H), 256, smem_attn>>>(r_w_bias, r_r_bias);

    // 3) output projection
    out_kernel<<<dim3(F / 128, S / 128), 256>>>(Wo, bo, out);
}